// round 3
// baseline (speedup 1.0000x reference)
#include <cuda_runtime.h>
#include <cstdint>

#define E_TILE   64
#define THREADS  512
#define F_DIM    32
#define H_DIM    128
#define IN_DIM   321
#define K1PAD    336     // 321 padded to multiple of 16
#define HID      512
#define OUT_DIM  256
#define XLD      340     // 336 + 4 pad -> conflict-friendly bank stride (20 mod 32)
#define HLD      516     // 512 + 4 pad -> bank stride 4 mod 32 (conflict-free A-frag)

// tf32-rounded weights (padded W1), written by prologue kernel each launch.
__device__ __align__(16) float g_W1t[K1PAD * HID];
__device__ __align__(16) float g_W2t[HID * HID];
__device__ __align__(16) float g_W3t[HID * OUT_DIM];

__device__ __forceinline__ float tf32r(float x) {
    unsigned u;
    asm("cvt.rna.tf32.f32 %0, %1;" : "=r"(u) : "f"(x));
    return __uint_as_float(u);
}

__global__ void convert_weights_kernel(const float* __restrict__ W1,
                                       const float* __restrict__ W2,
                                       const float* __restrict__ W3) {
    int i = blockIdx.x * blockDim.x + threadIdx.x;
    const int n1 = K1PAD * HID, n2 = HID * HID, n3 = HID * OUT_DIM;
    if (i < n1) {
        int r = i / HID, c = i % HID;
        g_W1t[i] = (r < IN_DIM) ? tf32r(W1[r * HID + c]) : 0.f;
        return;
    }
    i -= n1;
    if (i < n2) { g_W2t[i] = tf32r(W2[i]); return; }
    i -= n2;
    if (i < n3) { g_W3t[i] = tf32r(W3[i]); }
}

// ---------------- cp.async helpers ----------------
__device__ __forceinline__ void cp16(uint32_t saddr, const void* gptr) {
    asm volatile("cp.async.ca.shared.global [%0], [%1], 16;" :: "r"(saddr), "l"(gptr));
}
__device__ __forceinline__ void cp_commit() { asm volatile("cp.async.commit_group;"); }
template <int N> __device__ __forceinline__ void cp_wait() {
    asm volatile("cp.async.wait_group %0;" :: "n"(N));
}

__device__ __forceinline__ void mma_tf32(float c[4], const uint32_t a[4],
                                         uint32_t b0, uint32_t b1) {
    asm volatile(
        "mma.sync.aligned.m16n8k8.row.col.f32.tf32.tf32.f32 "
        "{%0,%1,%2,%3}, {%4,%5,%6,%7}, {%8,%9}, {%0,%1,%2,%3};"
        : "+f"(c[0]), "+f"(c[1]), "+f"(c[2]), "+f"(c[3])
        : "r"(a[0]), "r"(a[1]), "r"(a[2]), "r"(a[3]), "r"(b0), "r"(b1));
}

// One fused GEMM: [64, K] (smem, tf32) x [K, N] (global tf32, staged) -> acc regs.
// Warp grid 2(M) x 8(N). NT = n8-tiles per warp (8 -> N=512, 4 -> N=256).
template <int N, int NT, int NSTG>
__device__ __forceinline__ void run_gemm(const float* __restrict__ Wg,
                                         const float* __restrict__ As, int lda,
                                         float* Bst, float (&acc)[2][8][4],
                                         int wm, int wn, int g, int tig, int tid) {
    constexpr int BLD = N + 8;
    constexpr int CP_ITERS = (16 * N / 4) / THREADS;  // float4 per thread per stage
    uint32_t bst_base = (uint32_t)__cvta_generic_to_shared(Bst);

#pragma unroll
    for (int mt = 0; mt < 2; mt++)
#pragma unroll
        for (int nt = 0; nt < NT; nt++)
#pragma unroll
            for (int r = 0; r < 4; r++) acc[mt][nt][r] = 0.f;

    auto stage_cp = [&](int s, int buf) {
#pragma unroll
        for (int it = 0; it < CP_ITERS; it++) {
            int idx = it * THREADS + tid;           // float4 index within stage
            int r = idx / (N / 4);
            int c = idx % (N / 4);
            uint32_t dst = bst_base + (uint32_t)((buf * 16 + r) * BLD + c * 4) * 4u;
            cp16(dst, Wg + (size_t)(s * 16 + r) * N + c * 4);
        }
        cp_commit();
    };

    stage_cp(0, 0);
    for (int s = 0; s < NSTG; s++) {
        if (s + 1 < NSTG) { stage_cp(s + 1, (s + 1) & 1); cp_wait<1>(); }
        else              { cp_wait<0>(); }
        __syncthreads();
        const float* B = Bst + (s & 1) * 16 * BLD;
#pragma unroll
        for (int k8 = 0; k8 < 2; k8++) {
            int kg = s * 16 + k8 * 8;
            uint32_t a[2][4];
#pragma unroll
            for (int mt = 0; mt < 2; mt++) {
                const float* ar = As + (wm * 32 + mt * 16 + g) * lda + kg + tig;
                a[mt][0] = __float_as_uint(ar[0]);
                a[mt][1] = __float_as_uint(ar[8 * lda]);
                a[mt][2] = __float_as_uint(ar[4]);
                a[mt][3] = __float_as_uint(ar[8 * lda + 4]);
            }
#pragma unroll
            for (int nt = 0; nt < NT; nt++) {
                int col = wn * (NT * 8) + nt * 8 + g;
                uint32_t b0 = __float_as_uint(B[(k8 * 8 + tig) * BLD + col]);
                uint32_t b1 = __float_as_uint(B[(k8 * 8 + tig + 4) * BLD + col]);
                mma_tf32(acc[0][nt], a[0], b0, b1);
                mma_tf32(acc[1][nt], a[1], b0, b1);
            }
        }
        __syncthreads();  // buffer (s&1) now reusable next iteration
    }
}

__global__ void __launch_bounds__(THREADS, 1)
edge_mlp_kernel(const float* __restrict__ nf, const float* __restrict__ nh,
                const int* __restrict__ src_idx, const int* __restrict__ dst_idx,
                const float* __restrict__ dist,
                const float* __restrict__ b1, const float* __restrict__ b2,
                const float* __restrict__ b3,
                float* __restrict__ out, int E) {
    extern __shared__ float smem[];
    float* Xs = smem;                   // [64][XLD]
    float* Hs = smem + E_TILE * XLD;    // [64][HLD]

    int tid = threadIdx.x;
    int wid = tid >> 5;
    int lane = tid & 31;
    int g = lane >> 2, tig = lane & 3;
    int wm = wid >> 3, wn = wid & 7;    // 2 x 8 warp grid
    int e0 = blockIdx.x * E_TILE;

    // ---- gather: x = [dst_feat(32) | dst_hid(128) | src_feat(32) | dst_hid(128) | dist | 0pad] ----
    {
        int ebase = wid * 4;  // 4 edges per warp
#pragma unroll
        for (int q = 0; q < 4; q++) {
            int ee = ebase + q;
            int edge = e0 + ee;
            int d  = (edge < E) ? dst_idx[edge] : 0;
            int sn = (edge < E) ? src_idx[edge] : 0;
            float* xr = Xs + ee * XLD;
            xr[lane]       = tf32r(nf[(size_t)d * F_DIM + lane]);
            xr[160 + lane] = tf32r(nf[(size_t)sn * F_DIM + lane]);
#pragma unroll
            for (int j = 0; j < 4; j++) {
                float v = tf32r(nh[(size_t)d * H_DIM + j * 32 + lane]);
                xr[32  + j * 32 + lane] = v;
                xr[192 + j * 32 + lane] = v;
            }
            if (lane < 16)
                xr[320 + lane] = (lane == 0) ? tf32r((edge < E) ? dist[edge] : 0.f) : 0.f;
        }
    }
    __syncthreads();

    float acc[2][8][4];

    // ---- layer 1: Xs[64,336] @ W1t[336,512] -> Hs (B staged in free Hs region) ----
    run_gemm<HID, 8, K1PAD / 16>(g_W1t, Xs, XLD, Hs, acc, wm, wn, g, tig, tid);
#pragma unroll
    for (int mt = 0; mt < 2; mt++)
#pragma unroll
        for (int nt = 0; nt < 8; nt++) {
            int col = wn * 64 + nt * 8 + 2 * tig;
            float bb0 = __ldg(&b1[col]), bb1 = __ldg(&b1[col + 1]);
            int r0 = wm * 32 + mt * 16 + g;
            Hs[r0 * HLD + col]           = tf32r(fmaxf(acc[mt][nt][0] + bb0, 0.f));
            Hs[r0 * HLD + col + 1]       = tf32r(fmaxf(acc[mt][nt][1] + bb1, 0.f));
            Hs[(r0 + 8) * HLD + col]     = tf32r(fmaxf(acc[mt][nt][2] + bb0, 0.f));
            Hs[(r0 + 8) * HLD + col + 1] = tf32r(fmaxf(acc[mt][nt][3] + bb1, 0.f));
        }
    __syncthreads();

    // ---- layer 2: Hs @ W2t[512,512] -> Hs (B staged in Xs region) ----
    run_gemm<HID, 8, HID / 16>(g_W2t, Hs, HLD, Xs, acc, wm, wn, g, tig, tid);
#pragma unroll
    for (int mt = 0; mt < 2; mt++)
#pragma unroll
        for (int nt = 0; nt < 8; nt++) {
            int col = wn * 64 + nt * 8 + 2 * tig;
            float bb0 = __ldg(&b2[col]), bb1 = __ldg(&b2[col + 1]);
            int r0 = wm * 32 + mt * 16 + g;
            Hs[r0 * HLD + col]           = tf32r(fmaxf(acc[mt][nt][0] + bb0, 0.f));
            Hs[r0 * HLD + col + 1]       = tf32r(fmaxf(acc[mt][nt][1] + bb1, 0.f));
            Hs[(r0 + 8) * HLD + col]     = tf32r(fmaxf(acc[mt][nt][2] + bb0, 0.f));
            Hs[(r0 + 8) * HLD + col + 1] = tf32r(fmaxf(acc[mt][nt][3] + bb1, 0.f));
        }
    __syncthreads();

    // ---- layer 3: Hs @ W3t[512,256] -> out (B staged in Xs region) ----
    run_gemm<OUT_DIM, 4, HID / 16>(g_W3t, Hs, HLD, Xs, acc, wm, wn, g, tig, tid);
#pragma unroll
    for (int mt = 0; mt < 2; mt++)
#pragma unroll
        for (int nt = 0; nt < 4; nt++) {
            int col = wn * 32 + nt * 8 + 2 * tig;
            float bb0 = __ldg(&b3[col]), bb1 = __ldg(&b3[col + 1]);
            int r0 = wm * 32 + mt * 16 + g;
            int edge0 = e0 + r0;
            if (edge0 < E) {
                float2 v = make_float2(acc[mt][nt][0] + bb0, acc[mt][nt][1] + bb1);
                *reinterpret_cast<float2*>(&out[(size_t)edge0 * OUT_DIM + col]) = v;
            }
            int edge1 = e0 + r0 + 8;
            if (edge1 < E) {
                float2 v = make_float2(acc[mt][nt][2] + bb0, acc[mt][nt][3] + bb1);
                *reinterpret_cast<float2*>(&out[(size_t)edge1 * OUT_DIM + col]) = v;
            }
        }
}

extern "C" void kernel_launch(void* const* d_in, const int* in_sizes, int n_in,
                              void* d_out, int out_size) {
    const float* nf   = (const float*)d_in[0];
    const float* nh   = (const float*)d_in[1];
    const int*   srci = (const int*)d_in[2];
    const int*   dsti = (const int*)d_in[3];
    const float* dist = (const float*)d_in[4];
    const float* W1   = (const float*)d_in[5];
    const float* b1   = (const float*)d_in[6];
    const float* W2   = (const float*)d_in[7];
    const float* b2   = (const float*)d_in[8];
    const float* W3   = (const float*)d_in[9];
    const float* b3   = (const float*)d_in[10];
    float* out = (float*)d_out;

    int E = in_sizes[2];

    const int total_w = K1PAD * HID + HID * HID + HID * OUT_DIM;
    convert_weights_kernel<<<(total_w + 511) / 512, 512>>>(W1, W2, W3);

    const int smem_bytes = (E_TILE * XLD + E_TILE * HLD) * (int)sizeof(float);
    cudaFuncSetAttribute(edge_mlp_kernel,
                         cudaFuncAttributeMaxDynamicSharedMemorySize, smem_bytes);

    int grid = (E + E_TILE - 1) / E_TILE;
    edge_mlp_kernel<<<grid, THREADS, smem_bytes>>>(nf, nh, srci, dsti, dist,
                                                   b1, b2, b3, out, E);
}

// round 5
// speedup vs baseline: 1.2327x; 1.2327x over previous
#include <cuda_runtime.h>
#include <cstdint>

#define NN      50000
#define HID     512
#define OUT_DIM 256
#define E_TILE  64
#define THREADS 512
#define AROW    520          // 512 + 8 pad (8 mod 32 -> 2-way max on frag LDS64)

// ---------------- device scratch ----------------
__device__ __align__(16) float g_PD[(size_t)NN * HID];   // [nf|nh] @ W1comb + b1
__device__ __align__(16) float g_PS[(size_t)NN * HID];   // nf @ W1c
__device__ __align__(16) float g_W1comb[160 * HID];
__device__ __align__(16) float g_W1c[32 * HID];
__device__ __align__(16) float g_W2p[HID * HID];         // pair-permuted tf32
__device__ __align__(16) float g_W3p[HID * OUT_DIM];     // pair-permuted tf32

__device__ __forceinline__ float tf32r(float x) {
    unsigned u; asm("cvt.rna.tf32.f32 %0, %1;" : "=r"(u) : "f"(x));
    return __uint_as_float(u);
}
__device__ __forceinline__ void cp16(uint32_t saddr, const void* gptr) {
    asm volatile("cp.async.ca.shared.global [%0], [%1], 16;" :: "r"(saddr), "l"(gptr));
}
__device__ __forceinline__ void cp_commit() { asm volatile("cp.async.commit_group;"); }
template <int N> __device__ __forceinline__ void cp_wait() {
    asm volatile("cp.async.wait_group %0;" :: "n"(N));
}
__device__ __forceinline__ uint32_t s2u(const void* p) {
    uint32_t a;
    asm("{ .reg .u64 t; cvta.to.shared.u64 t, %1; cvt.u32.u64 %0, t; }" : "=r"(a) : "l"(p));
    return a;
}
__device__ __forceinline__ void mma_tf32s(float c[4], const uint32_t a[4],
                                          uint32_t b0, uint32_t b1) {
    asm volatile(
        "mma.sync.aligned.m16n8k8.row.col.f32.tf32.tf32.f32 "
        "{%0,%1,%2,%3}, {%4,%5,%6,%7}, {%8,%9}, {%0,%1,%2,%3};"
        : "+f"(c[0]), "+f"(c[1]), "+f"(c[2]), "+f"(c[3])
        : "r"(a[0]), "r"(a[1]), "r"(a[2]), "r"(a[3]), "r"(b0), "r"(b1));
}

// ================= prologue 0: weight transforms =================
// pair-permuted layout: value W[k][n] (K-major) at float index
//   ((k>>3)*N + n)*8 + (k&3)*2 + ((k&7)>>2)
__global__ void conv_kernel(const float* __restrict__ W1, const float* __restrict__ W2,
                            const float* __restrict__ W3) {
    int i = blockIdx.x * blockDim.x + threadIdx.x;
    if (i < 160 * 512) {
        int r = i >> 9, c = i & 511;
        float v = W1[r * 512 + c];
        if (r >= 32) v += W1[(r + 160) * 512 + c];
        g_W1comb[i] = tf32r(v);
        return;
    }
    i -= 160 * 512;
    if (i < 32 * 512) {
        int r = i >> 9, c = i & 511;
        g_W1c[i] = tf32r(W1[(160 + r) * 512 + c]);
        return;
    }
    i -= 32 * 512;
    if (i < 512 * 512) {
        int k = i >> 9, n = i & 511;
        int r = k & 7;
        size_t pos = ((size_t)(k >> 3) * 512 + n) * 8 + (r & 3) * 2 + (r >> 2);
        g_W2p[pos] = tf32r(W2[k * 512 + n]);
        return;
    }
    i -= 512 * 512;
    {
        int k = i >> 8, n = i & 255;
        int r = k & 7;
        size_t pos = ((size_t)(k >> 3) * 256 + n) * 8 + (r & 3) * 2 + (r >> 2);
        g_W3p[pos] = tf32r(W3[k * 256 + n]);
    }
}

// ================= prologue GEMM machinery (round-1 proven) =================
template <int N, int NT, int NSTG, int NTHR>
__device__ __forceinline__ void run_gemm(const float* __restrict__ Wg,
                                         const float* __restrict__ As, int lda,
                                         float* Bst, float (&acc)[2][8][4],
                                         int wm, int wn, int g, int tig, int tid) {
    constexpr int BLD = N + 8;
    constexpr int CP_ITERS = (16 * N / 4) / NTHR;
    uint32_t bst_base = s2u(Bst);
#pragma unroll
    for (int mt = 0; mt < 2; mt++)
#pragma unroll
        for (int nt = 0; nt < NT; nt++)
#pragma unroll
            for (int r = 0; r < 4; r++) acc[mt][nt][r] = 0.f;

    auto stage_cp = [&](int s, int buf) {
#pragma unroll
        for (int it = 0; it < CP_ITERS; it++) {
            int idx = it * NTHR + tid;
            int r = idx / (N / 4), c = idx % (N / 4);
            uint32_t dst = bst_base + (uint32_t)((buf * 16 + r) * BLD + c * 4) * 4u;
            cp16(dst, Wg + (size_t)(s * 16 + r) * N + c * 4);
        }
        cp_commit();
    };

    stage_cp(0, 0);
    for (int s = 0; s < NSTG; s++) {
        if (s + 1 < NSTG) { stage_cp(s + 1, (s + 1) & 1); cp_wait<1>(); }
        else              { cp_wait<0>(); }
        __syncthreads();
        const float* B = Bst + (s & 1) * 16 * BLD;
#pragma unroll
        for (int k8 = 0; k8 < 2; k8++) {
            int kg = s * 16 + k8 * 8;
            uint32_t a[2][4];
#pragma unroll
            for (int mt = 0; mt < 2; mt++) {
                const float* ar = As + (wm * 32 + mt * 16 + g) * lda + kg + tig;
                a[mt][0] = __float_as_uint(ar[0]);
                a[mt][1] = __float_as_uint(ar[8 * lda]);
                a[mt][2] = __float_as_uint(ar[4]);
                a[mt][3] = __float_as_uint(ar[8 * lda + 4]);
            }
#pragma unroll
            for (int nt = 0; nt < NT; nt++) {
                int col = wn * (NT * 8) + nt * 8 + g;
                uint32_t b0 = __float_as_uint(B[(k8 * 8 + tig) * BLD + col]);
                uint32_t b1 = __float_as_uint(B[(k8 * 8 + tig + 4) * BLD + col]);
                mma_tf32s(acc[0][nt], a[0], b0, b1);
                mma_tf32s(acc[1][nt], a[1], b0, b1);
            }
        }
        __syncthreads();
    }
}

// ================= prologue 1: per-node PD/PS =================
__global__ void __launch_bounds__(512, 1)
pdps_kernel(const float* __restrict__ nf, const float* __restrict__ nh,
            const float* __restrict__ b1) {
    extern __shared__ float sm[];
    float* As = sm;               // [64][164]
    float* Bst = sm + 64 * 164;   // [2][16][520]
    int tid = threadIdx.x, wid = tid >> 5, lane = tid & 31;
    int g = lane >> 2, tig = lane & 3, wm = wid >> 3, wn = wid & 7;
    int n0 = blockIdx.x * 64;
    {
        int rr = wid * 4;
#pragma unroll
        for (int q = 0; q < 4; q++) {
            int r = rr + q, n = n0 + r;
            bool ok = n < NN; int ni = ok ? n : 0;
            float* ar = As + r * 164;
            ar[lane] = ok ? tf32r(nf[(size_t)ni * 32 + lane]) : 0.f;
#pragma unroll
            for (int j = 0; j < 4; j++)
                ar[32 + j * 32 + lane] = ok ? tf32r(nh[(size_t)ni * 128 + j * 32 + lane]) : 0.f;
            if (lane < 4) ar[160 + lane] = 0.f;
        }
    }
    __syncthreads();
    float acc[2][8][4];
    run_gemm<512, 8, 10, 512>(g_W1comb, As, 164, Bst, acc, wm, wn, g, tig, tid);
#pragma unroll
    for (int mt = 0; mt < 2; mt++)
#pragma unroll
        for (int nt = 0; nt < 8; nt++) {
            int col = wn * 64 + nt * 8 + 2 * tig;
            float bb0 = __ldg(&b1[col]), bb1 = __ldg(&b1[col + 1]);
            int r0 = wm * 32 + mt * 16 + g;
            if (n0 + r0 < NN)
                *(float2*)(g_PD + (size_t)(n0 + r0) * 512 + col) =
                    make_float2(acc[mt][nt][0] + bb0, acc[mt][nt][1] + bb1);
            if (n0 + r0 + 8 < NN)
                *(float2*)(g_PD + (size_t)(n0 + r0 + 8) * 512 + col) =
                    make_float2(acc[mt][nt][2] + bb0, acc[mt][nt][3] + bb1);
        }
    run_gemm<512, 8, 2, 512>(g_W1c, As, 164, Bst, acc, wm, wn, g, tig, tid);
#pragma unroll
    for (int mt = 0; mt < 2; mt++)
#pragma unroll
        for (int nt = 0; nt < 8; nt++) {
            int col = wn * 64 + nt * 8 + 2 * tig;
            int r0 = wm * 32 + mt * 16 + g;
            if (n0 + r0 < NN)
                *(float2*)(g_PS + (size_t)(n0 + r0) * 512 + col) =
                    make_float2(acc[mt][nt][0], acc[mt][nt][1]);
            if (n0 + r0 + 8 < NN)
                *(float2*)(g_PS + (size_t)(n0 + r0 + 8) * 512 + col) =
                    make_float2(acc[mt][nt][2], acc[mt][nt][3]);
        }
}

// ================= main fused kernel (layers 2+3) =================
// smem floats: As[0,33280) | Bst[33280,49664) | sd | ss | sdist
#define SM_AS   0
#define SM_BST  33280
#define SM_SD   49664
#define SM_SS   49728
#define SM_DIST 49792
#define SM_TOT  49856

// pair-layout GEMM: A in smem pair layout, B pre-permuted in global, linear staging.
template <int N, int NT>
__device__ __forceinline__ void gemm_tc(const float* __restrict__ Wp,
                                        const float* __restrict__ As, float* Bst,
                                        float (&acc)[2][8][4],
                                        int wm, int wn, int g, int tig, int tid) {
    constexpr int NSTG = 32;
    constexpr int STGF = 16 * N;                 // floats per stage
    constexpr int CP_ITERS = STGF / 4 / THREADS; // float4 per thread
    uint32_t bbase = s2u(Bst);
#pragma unroll
    for (int mt = 0; mt < 2; mt++)
#pragma unroll
        for (int nt = 0; nt < NT; nt++)
#pragma unroll
            for (int r = 0; r < 4; r++) acc[mt][nt][r] = 0.f;

    auto docp = [&](int s) {
        const float* src = Wp + (size_t)s * STGF;
        uint32_t dst = bbase + (uint32_t)((s & 1) * STGF) * 4u;
#pragma unroll
        for (int it = 0; it < CP_ITERS; it++) {
            int idx = it * THREADS + tid;
            cp16(dst + (uint32_t)idx * 16u, src + idx * 4);
        }
        cp_commit();
    };

    docp(0);
    for (int s = 0; s < NSTG; s++) {
        cp_wait<0>();
        __syncthreads();                 // buf[s&1] ready; prior reads of buf[(s+1)&1] done
        if (s + 1 < NSTG) docp(s + 1);   // overlaps the MMA body below
        const float* B = Bst + (s & 1) * STGF;
        int kb8b = s * 2;
#pragma unroll
        for (int kb = 0; kb < 2; kb++) {
            uint2 pa[2][2];
#pragma unroll
            for (int mt = 0; mt < 2; mt++) {
                const float* ar = As + (wm * 32 + mt * 16 + g) * AROW + (kb8b + kb) * 8 + tig * 2;
                pa[mt][0] = *(const uint2*)ar;
                pa[mt][1] = *(const uint2*)(ar + 8 * AROW);
            }
#pragma unroll
            for (int nt = 0; nt < NT; nt++) {
                int col = wn * (NT * 8) + nt * 8 + g;
                uint2 pb = *(const uint2*)(B + ((kb * N + col) * 4 + tig) * 2);
                uint32_t a0[4] = {pa[0][0].x, pa[0][1].x, pa[0][0].y, pa[0][1].y};
                mma_tf32s(acc[0][nt], a0, pb.x, pb.y);
                uint32_t a1[4] = {pa[1][0].x, pa[1][1].x, pa[1][0].y, pa[1][1].y};
                mma_tf32s(acc[1][nt], a1, pb.x, pb.y);
            }
        }
    }
    __syncthreads();
}

// slot of column c within its 8-col pair group
__device__ __forceinline__ int slot8(int r) { return (r < 4) ? 2 * r : 2 * (r - 4) + 1; }

__global__ void __launch_bounds__(THREADS, 1)
edge_kernel(const int* __restrict__ src_idx, const int* __restrict__ dst_idx,
            const float* __restrict__ dist, const float* __restrict__ w320,
            const float* __restrict__ b2, const float* __restrict__ b3,
            float* __restrict__ out, int E) {
    extern __shared__ float smf[];
    float* As  = smf + SM_AS;
    float* Bst = smf + SM_BST;
    int* sd = (int*)(smf + SM_SD);
    int* ss = (int*)(smf + SM_SS);
    float* sdist = smf + SM_DIST;

    int tid = threadIdx.x, wid = tid >> 5, lane = tid & 31;
    int g = lane >> 2, tig = lane & 3, wm = wid >> 3, wn = wid & 7;
    int e0 = blockIdx.x * E_TILE;

    if (tid < E_TILE) {
        int e = e0 + tid;
        bool ok = e < E;
        sd[tid] = ok ? dst_idx[e] : 0;
        ss[tid] = ok ? src_idx[e] : 0;
        sdist[tid] = ok ? dist[e] : 0.f;
    }
    __syncthreads();

    // ---- gather h1 = relu(PD[dst] + PS[src] + dist*w320) into As (pair layout) ----
    {
        int e = tid >> 3, l8 = tid & 7;
        const float* pd = g_PD + (size_t)sd[e] * HID;
        const float* ps = g_PS + (size_t)ss[e] * HID;
        float dd = sdist[e];
        float* arow = As + e * AROW;
#pragma unroll
        for (int j = 0; j < 16; j++) {
            int c = (j * 8 + l8) * 4;
            float4 a = *(const float4*)(pd + c);
            float4 b = *(const float4*)(ps + c);
            float4 w = __ldg((const float4*)(w320 + c));
            float v0 = tf32r(fmaxf(fmaf(dd, w.x, a.x + b.x), 0.f));
            float v1 = tf32r(fmaxf(fmaf(dd, w.y, a.y + b.y), 0.f));
            float v2 = tf32r(fmaxf(fmaf(dd, w.z, a.z + b.z), 0.f));
            float v3 = tf32r(fmaxf(fmaf(dd, w.w, a.w + b.w), 0.f));
            int base = (c >> 3) * 8;
            if ((c & 7) == 0) {
                arow[base + 0] = v0; arow[base + 2] = v1;
                arow[base + 4] = v2; arow[base + 6] = v3;
            } else {
                arow[base + 1] = v0; arow[base + 3] = v1;
                arow[base + 5] = v2; arow[base + 7] = v3;
            }
        }
    }
    __syncthreads();

    float acc[2][8][4];

    // ---- layer 2 ----
    gemm_tc<HID, 8>(g_W2p, As, Bst, acc, wm, wn, g, tig, tid);
    // epilogue: relu(acc + b2) -> As pair layout
    {
        int s0 = (tig < 2) ? 4 * tig : 4 * tig - 7;  // slot of col (2*tig); slot1 = s0+2
#pragma unroll
        for (int mt = 0; mt < 2; mt++)
#pragma unroll
            for (int nt = 0; nt < 8; nt++) {
                int colb = wn * 64 + nt * 8;
                float bb0 = __ldg(&b2[colb + 2 * tig]);
                float bb1 = __ldg(&b2[colb + 2 * tig + 1]);
                int r0 = wm * 32 + mt * 16 + g;
                float* p0 = As + r0 * AROW + colb;
                float* p1 = As + (r0 + 8) * AROW + colb;
                p0[s0]     = tf32r(fmaxf(acc[mt][nt][0] + bb0, 0.f));
                p0[s0 + 2] = tf32r(fmaxf(acc[mt][nt][1] + bb1, 0.f));
                p1[s0]     = tf32r(fmaxf(acc[mt][nt][2] + bb0, 0.f));
                p1[s0 + 2] = tf32r(fmaxf(acc[mt][nt][3] + bb1, 0.f));
            }
    }
    __syncthreads();

    // ---- layer 3 ----
    gemm_tc<OUT_DIM, 4>(g_W3p, As, Bst, acc, wm, wn, g, tig, tid);
#pragma unroll
    for (int mt = 0; mt < 2; mt++)
#pragma unroll
        for (int nt = 0; nt < 4; nt++) {
            int c0 = wn * 32 + nt * 8 + 2 * tig;
            float bb0 = __ldg(&b3[c0]), bb1 = __ldg(&b3[c0 + 1]);
            int r0 = wm * 32 + mt * 16 + g;
            int edge0 = e0 + r0;
            if (edge0 < E)
                *(float2*)(out + (size_t)edge0 * OUT_DIM + c0) =
                    make_float2(acc[mt][nt][0] + bb0, acc[mt][nt][1] + bb1);
            int edge1 = e0 + r0 + 8;
            if (edge1 < E)
                *(float2*)(out + (size_t)edge1 * OUT_DIM + c0) =
                    make_float2(acc[mt][nt][2] + bb0, acc[mt][nt][3] + bb1);
        }
}

extern "C" void kernel_launch(void* const* d_in, const int* in_sizes, int n_in,
                              void* d_out, int out_size) {
    const float* nf   = (const float*)d_in[0];
    const float* nh   = (const float*)d_in[1];
    const int*   srci = (const int*)d_in[2];
    const int*   dsti = (const int*)d_in[3];
    const float* dist = (const float*)d_in[4];
    const float* W1   = (const float*)d_in[5];
    const float* b1   = (const float*)d_in[6];
    const float* W2   = (const float*)d_in[7];
    const float* b2   = (const float*)d_in[8];
    const float* W3   = (const float*)d_in[9];
    const float* b3   = (const float*)d_in[10];
    float* out = (float*)d_out;
    int E = in_sizes[2];

    const int total_c = 160 * 512 + 32 * 512 + 512 * 512 + 512 * 256;
    conv_kernel<<<(total_c + 511) / 512, 512>>>(W1, W2, W3);

    const int pro_smem = (64 * 164 + 2 * 16 * 520) * (int)sizeof(float);
    cudaFuncSetAttribute(pdps_kernel, cudaFuncAttributeMaxDynamicSharedMemorySize, pro_smem);
    pdps_kernel<<<(NN + 63) / 64, 512, pro_smem>>>(nf, nh, b1);

    const int main_smem = SM_TOT * (int)sizeof(float);
    cudaFuncSetAttribute(edge_kernel, cudaFuncAttributeMaxDynamicSharedMemorySize, main_smem);
    int grid = (E + E_TILE - 1) / E_TILE;
    edge_kernel<<<grid, THREADS, main_smem>>>(srci, dsti, dist, W1 + 320 * 512,
                                              b2, b3, out, E);
}

// round 6
// speedup vs baseline: 2.4590x; 1.9949x over previous
#include <cuda_runtime.h>
#include <cuda_fp16.h>
#include <cstdint>

#define NN      50000
#define HID     512
#define OUT_DIM 256
#define E_TILE  64
#define THREADS 512
#define APITCH  264   // uint32 (fp16-pair) pitch: 264 mod 32 = 8 -> conflict-free frag LDS64

// ---------------- device scratch ----------------
__device__ __align__(16) float    g_PD[(size_t)NN * HID];   // [nf|nh]@W1comb + b1 (fp32)
__device__ __align__(16) float    g_PS[(size_t)NN * HID];   // nf@W1c (fp32)
__device__ __align__(16) float    g_W1comb[160 * HID];
__device__ __align__(16) float    g_W1c[32 * HID];
__device__ __align__(16) uint32_t g_W2p[HID * HID / 2];     // fp16 pair-permuted
__device__ __align__(16) uint32_t g_W3p[HID * OUT_DIM / 2]; // fp16 pair-permuted

__device__ __forceinline__ float tf32r(float x) {
    unsigned u; asm("cvt.rna.tf32.f32 %0, %1;" : "=r"(u) : "f"(x));
    return __uint_as_float(u);
}
__device__ __forceinline__ uint32_t packh2(float lo, float hi) {
    uint32_t u; asm("cvt.rn.f16x2.f32 %0, %1, %2;" : "=r"(u) : "f"(hi), "f"(lo));
    return u;
}
__device__ __forceinline__ void cp16(uint32_t saddr, const void* gptr) {
    asm volatile("cp.async.ca.shared.global [%0], [%1], 16;" :: "r"(saddr), "l"(gptr));
}
__device__ __forceinline__ void cp_commit() { asm volatile("cp.async.commit_group;"); }
template <int N> __device__ __forceinline__ void cp_wait() {
    asm volatile("cp.async.wait_group %0;" :: "n"(N));
}
__device__ __forceinline__ uint32_t s2u(const void* p) {
    uint32_t a;
    asm("{ .reg .u64 t; cvta.to.shared.u64 t, %1; cvt.u32.u64 %0, t; }" : "=r"(a) : "l"(p));
    return a;
}
__device__ __forceinline__ void mma_tf32s(float c[4], const uint32_t a[4],
                                          uint32_t b0, uint32_t b1) {
    asm volatile(
        "mma.sync.aligned.m16n8k8.row.col.f32.tf32.tf32.f32 "
        "{%0,%1,%2,%3}, {%4,%5,%6,%7}, {%8,%9}, {%0,%1,%2,%3};"
        : "+f"(c[0]), "+f"(c[1]), "+f"(c[2]), "+f"(c[3])
        : "r"(a[0]), "r"(a[1]), "r"(a[2]), "r"(a[3]), "r"(b0), "r"(b1));
}
__device__ __forceinline__ void mma_h(float c[4], uint32_t a0, uint32_t a1,
                                      uint32_t a2, uint32_t a3,
                                      uint32_t b0, uint32_t b1) {
    asm volatile(
        "mma.sync.aligned.m16n8k16.row.col.f32.f16.f16.f32 "
        "{%0,%1,%2,%3}, {%4,%5,%6,%7}, {%8,%9}, {%0,%1,%2,%3};"
        : "+f"(c[0]), "+f"(c[1]), "+f"(c[2]), "+f"(c[3])
        : "r"(a0), "r"(a1), "r"(a2), "r"(a3), "r"(b0), "r"(b1));
}
// slot of pair p (0..7) within a 16-k group: interleave (p, p+4) adjacent
__device__ __forceinline__ int slotp(int p) { return ((p & 3) << 1) | (p >> 2); }

// ================= prologue 0: weight transforms =================
__global__ void conv_kernel(const float* __restrict__ W1, const float* __restrict__ W2,
                            const float* __restrict__ W3) {
    int i = blockIdx.x * blockDim.x + threadIdx.x;
    if (i < 160 * 512) {                    // W1comb (fp32/tf32)
        int r = i >> 9, c = i & 511;
        float v = W1[r * 512 + c];
        if (r >= 32) v += W1[(r + 160) * 512 + c];
        g_W1comb[i] = tf32r(v);
        return;
    }
    i -= 160 * 512;
    if (i < 32 * 512) {                     // W1c (fp32/tf32)
        int r = i >> 9, c = i & 511;
        g_W1c[i] = tf32r(W1[(160 + r) * 512 + c]);
        return;
    }
    i -= 32 * 512;
    if (i < 512 * 512 / 2) {                // W2 -> fp16 pairs, permuted
        int kp = i >> 9, n = i & 511;       // kp: pair row (k = 2*kp)
        int k = kp << 1;
        int kg = kp >> 3, p = kp & 7;
        g_W2p[(size_t)(kg * 512 + n) * 8 + slotp(p)] =
            packh2(W2[k * 512 + n], W2[(k + 1) * 512 + n]);
        return;
    }
    i -= 512 * 512 / 2;
    {                                       // W3 -> fp16 pairs, permuted
        int kp = i >> 8, n = i & 255;
        int k = kp << 1;
        int kg = kp >> 3, p = kp & 7;
        g_W3p[(size_t)(kg * 256 + n) * 8 + slotp(p)] =
            packh2(W3[k * 256 + n], W3[(k + 1) * 256 + n]);
    }
}

// ================= prologue GEMM machinery (tf32, proven) =================
template <int N, int NT, int NSTG, int NTHR>
__device__ __forceinline__ void run_gemm(const float* __restrict__ Wg,
                                         const float* __restrict__ As, int lda,
                                         float* Bst, float (&acc)[2][8][4],
                                         int wm, int wn, int g, int tig, int tid) {
    constexpr int BLD = N + 8;
    constexpr int CP_ITERS = (16 * N / 4) / NTHR;
    uint32_t bst_base = s2u(Bst);
#pragma unroll
    for (int mt = 0; mt < 2; mt++)
#pragma unroll
        for (int nt = 0; nt < NT; nt++)
#pragma unroll
            for (int r = 0; r < 4; r++) acc[mt][nt][r] = 0.f;

    auto stage_cp = [&](int s, int buf) {
#pragma unroll
        for (int it = 0; it < CP_ITERS; it++) {
            int idx = it * NTHR + tid;
            int r = idx / (N / 4), c = idx % (N / 4);
            uint32_t dst = bst_base + (uint32_t)((buf * 16 + r) * BLD + c * 4) * 4u;
            cp16(dst, Wg + (size_t)(s * 16 + r) * N + c * 4);
        }
        cp_commit();
    };

    stage_cp(0, 0);
    for (int s = 0; s < NSTG; s++) {
        if (s + 1 < NSTG) { stage_cp(s + 1, (s + 1) & 1); cp_wait<1>(); }
        else              { cp_wait<0>(); }
        __syncthreads();
        const float* B = Bst + (s & 1) * 16 * BLD;
#pragma unroll
        for (int k8 = 0; k8 < 2; k8++) {
            int kg = s * 16 + k8 * 8;
            uint32_t a[2][4];
#pragma unroll
            for (int mt = 0; mt < 2; mt++) {
                const float* ar = As + (wm * 32 + mt * 16 + g) * lda + kg + tig;
                a[mt][0] = __float_as_uint(ar[0]);
                a[mt][1] = __float_as_uint(ar[8 * lda]);
                a[mt][2] = __float_as_uint(ar[4]);
                a[mt][3] = __float_as_uint(ar[8 * lda + 4]);
            }
#pragma unroll
            for (int nt = 0; nt < NT; nt++) {
                int col = wn * (NT * 8) + nt * 8 + g;
                uint32_t b0 = __float_as_uint(B[(k8 * 8 + tig) * BLD + col]);
                uint32_t b1 = __float_as_uint(B[(k8 * 8 + tig + 4) * BLD + col]);
                mma_tf32s(acc[0][nt], a[0], b0, b1);
                mma_tf32s(acc[1][nt], a[1], b0, b1);
            }
        }
        __syncthreads();
    }
}

// ================= prologue 1: per-node PD/PS =================
__global__ void __launch_bounds__(512, 1)
pdps_kernel(const float* __restrict__ nf, const float* __restrict__ nh,
            const float* __restrict__ b1) {
    extern __shared__ float sm[];
    float* As = sm;               // [64][164]
    float* Bst = sm + 64 * 164;   // [2][16][520]
    int tid = threadIdx.x, wid = tid >> 5, lane = tid & 31;
    int g = lane >> 2, tig = lane & 3, wm = wid >> 3, wn = wid & 7;
    int n0 = blockIdx.x * 64;
    {
        int rr = wid * 4;
#pragma unroll
        for (int q = 0; q < 4; q++) {
            int r = rr + q, n = n0 + r;
            bool ok = n < NN; int ni = ok ? n : 0;
            float* ar = As + r * 164;
            ar[lane] = ok ? tf32r(nf[(size_t)ni * 32 + lane]) : 0.f;
#pragma unroll
            for (int j = 0; j < 4; j++)
                ar[32 + j * 32 + lane] = ok ? tf32r(nh[(size_t)ni * 128 + j * 32 + lane]) : 0.f;
            if (lane < 4) ar[160 + lane] = 0.f;
        }
    }
    __syncthreads();
    float acc[2][8][4];
    run_gemm<512, 8, 10, 512>(g_W1comb, As, 164, Bst, acc, wm, wn, g, tig, tid);
#pragma unroll
    for (int mt = 0; mt < 2; mt++)
#pragma unroll
        for (int nt = 0; nt < 8; nt++) {
            int col = wn * 64 + nt * 8 + 2 * tig;
            float bb0 = __ldg(&b1[col]), bb1 = __ldg(&b1[col + 1]);
            int r0 = wm * 32 + mt * 16 + g;
            if (n0 + r0 < NN)
                *(float2*)(g_PD + (size_t)(n0 + r0) * 512 + col) =
                    make_float2(acc[mt][nt][0] + bb0, acc[mt][nt][1] + bb1);
            if (n0 + r0 + 8 < NN)
                *(float2*)(g_PD + (size_t)(n0 + r0 + 8) * 512 + col) =
                    make_float2(acc[mt][nt][2] + bb0, acc[mt][nt][3] + bb1);
        }
    run_gemm<512, 8, 2, 512>(g_W1c, As, 164, Bst, acc, wm, wn, g, tig, tid);
#pragma unroll
    for (int mt = 0; mt < 2; mt++)
#pragma unroll
        for (int nt = 0; nt < 8; nt++) {
            int col = wn * 64 + nt * 8 + 2 * tig;
            int r0 = wm * 32 + mt * 16 + g;
            if (n0 + r0 < NN)
                *(float2*)(g_PS + (size_t)(n0 + r0) * 512 + col) =
                    make_float2(acc[mt][nt][0], acc[mt][nt][1]);
            if (n0 + r0 + 8 < NN)
                *(float2*)(g_PS + (size_t)(n0 + r0 + 8) * 512 + col) =
                    make_float2(acc[mt][nt][2], acc[mt][nt][3]);
        }
}

// ================= main fused kernel (layers 2+3, fp16 MMA) =================
// smem uint32 units: Au[0,16896) | Bu[16896,33280) | sd | ss | sdist
#define SM_AU   0
#define SM_BU   16896
#define SM_SD   33280
#define SM_SS   33344
#define SM_DIST 33408
#define SM_TOT  33472

// fp16 GEMM: A pairs in smem (pair-permuted, pitch APITCH), B pre-permuted in global.
// K = 512 in 16 stages of k=32 (2 x 16-k groups per stage).
template <int N, int NT>
__device__ __forceinline__ void gemm_h(const uint32_t* __restrict__ Wp,
                                       const uint32_t* __restrict__ Au, uint32_t* Bu,
                                       float (&acc)[2][8][4],
                                       int wm, int wn, int g, int tig, int tid) {
    constexpr int NSTG = 16;
    constexpr int STGU = 16 * N;                  // uint32 per k=32 stage
    constexpr int CP_ITERS = STGU / 4 / THREADS;  // cp16 per thread
    uint32_t bbase = s2u(Bu);
#pragma unroll
    for (int mt = 0; mt < 2; mt++)
#pragma unroll
        for (int nt = 0; nt < NT; nt++)
#pragma unroll
            for (int r = 0; r < 4; r++) acc[mt][nt][r] = 0.f;

    auto docp = [&](int s) {
        const uint32_t* src = Wp + (size_t)s * STGU;
        uint32_t dst = bbase + (uint32_t)((s & 1) * STGU) * 4u;
#pragma unroll
        for (int it = 0; it < CP_ITERS; it++) {
            int idx = it * THREADS + tid;
            cp16(dst + (uint32_t)idx * 16u, src + idx * 4);
        }
        cp_commit();
    };

    docp(0);
    for (int s = 0; s < NSTG; s++) {
        cp_wait<0>();
        __syncthreads();
        if (s + 1 < NSTG) docp(s + 1);   // overlaps MMA body
        const uint32_t* B = Bu + (s & 1) * STGU;
#pragma unroll
        for (int kg = 0; kg < 2; kg++) {
            uint2 alo[2], ahi[2];
#pragma unroll
            for (int mt = 0; mt < 2; mt++) {
                const uint32_t* ar = Au + (wm * 32 + mt * 16 + g) * APITCH +
                                     (s * 2 + kg) * 8 + tig * 2;
                alo[mt] = *(const uint2*)ar;               // a0 (k..k+1), a2 (k+8..k+9)
                ahi[mt] = *(const uint2*)(ar + 8 * APITCH); // a1, a3
            }
#pragma unroll
            for (int nt = 0; nt < NT; nt++) {
                int col = wn * (NT * 8) + nt * 8 + g;
                uint2 pb = *(const uint2*)(B + kg * (N * 8) + col * 8 + tig * 2);
                mma_h(acc[0][nt], alo[0].x, ahi[0].x, alo[0].y, ahi[0].y, pb.x, pb.y);
                mma_h(acc[1][nt], alo[1].x, ahi[1].x, alo[1].y, ahi[1].y, pb.x, pb.y);
            }
        }
    }
    __syncthreads();
}

__global__ void __launch_bounds__(THREADS, 1)
edge_kernel(const int* __restrict__ src_idx, const int* __restrict__ dst_idx,
            const float* __restrict__ dist, const float* __restrict__ w320,
            const float* __restrict__ b2, const float* __restrict__ b3,
            float* __restrict__ out, int E) {
    extern __shared__ uint32_t smu[];
    uint32_t* Au = smu + SM_AU;
    uint32_t* Bu = smu + SM_BU;
    int* sd = (int*)(smu + SM_SD);
    int* ss = (int*)(smu + SM_SS);
    float* sdist = (float*)(smu + SM_DIST);

    int tid = threadIdx.x, wid = tid >> 5, lane = tid & 31;
    int g = lane >> 2, tig = lane & 3, wm = wid >> 3, wn = wid & 7;
    int e0 = blockIdx.x * E_TILE;

    if (tid < E_TILE) {
        int e = e0 + tid;
        bool ok = e < E;
        sd[tid] = ok ? dst_idx[e] : 0;
        ss[tid] = ok ? src_idx[e] : 0;
        sdist[tid] = ok ? dist[e] : 0.f;
    }
    __syncthreads();

    // ---- gather h1 = relu(PD[dst] + PS[src] + dist*w320) -> Au (fp16 pair layout) ----
    {
        int e = tid >> 3, l8 = tid & 7;
        const float* pd = g_PD + (size_t)sd[e] * HID;
        const float* ps = g_PS + (size_t)ss[e] * HID;
        float dd = sdist[e];
        uint32_t* arow = Au + e * APITCH;
#pragma unroll
        for (int j = 0; j < 16; j++) {
            int c = (j * 8 + l8) * 4;
            float4 a = *(const float4*)(pd + c);
            float4 b = *(const float4*)(ps + c);
            float4 w = __ldg((const float4*)(w320 + c));
            float v0 = fmaxf(fmaf(dd, w.x, a.x + b.x), 0.f);
            float v1 = fmaxf(fmaf(dd, w.y, a.y + b.y), 0.f);
            float v2 = fmaxf(fmaf(dd, w.z, a.z + b.z), 0.f);
            float v3 = fmaxf(fmaf(dd, w.w, a.w + b.w), 0.f);
            int p = (c >> 1) & 7;                 // even
            int base = ((c >> 4) << 3);
            arow[base + slotp(p)]     = packh2(v0, v1);
            arow[base + slotp(p + 1)] = packh2(v2, v3);
        }
    }
    __syncthreads();

    float acc[2][8][4];

    // ---- layer 2 ----
    gemm_h<HID, 8>(g_W2p, Au, Bu, acc, wm, wn, g, tig, tid);
    // epilogue: relu(acc + b2) -> Au fp16 pairs
    {
#pragma unroll
        for (int mt = 0; mt < 2; mt++)
#pragma unroll
            for (int nt = 0; nt < 8; nt++) {
                int c = wn * 64 + nt * 8 + 2 * tig;
                float bb0 = __ldg(&b2[c]), bb1 = __ldg(&b2[c + 1]);
                int r0 = wm * 32 + mt * 16 + g;
                int off = ((c >> 4) << 3) + slotp((c >> 1) & 7);
                Au[r0 * APITCH + off] =
                    packh2(fmaxf(acc[mt][nt][0] + bb0, 0.f), fmaxf(acc[mt][nt][1] + bb1, 0.f));
                Au[(r0 + 8) * APITCH + off] =
                    packh2(fmaxf(acc[mt][nt][2] + bb0, 0.f), fmaxf(acc[mt][nt][3] + bb1, 0.f));
            }
    }
    __syncthreads();

    // ---- layer 3 ----
    gemm_h<OUT_DIM, 4>(g_W3p, Au, Bu, acc, wm, wn, g, tig, tid);
#pragma unroll
    for (int mt = 0; mt < 2; mt++)
#pragma unroll
        for (int nt = 0; nt < 4; nt++) {
            int c0 = wn * 32 + nt * 8 + 2 * tig;
            float bb0 = __ldg(&b3[c0]), bb1 = __ldg(&b3[c0 + 1]);
            int r0 = wm * 32 + mt * 16 + g;
            int edge0 = e0 + r0;
            if (edge0 < E)
                *(float2*)(out + (size_t)edge0 * OUT_DIM + c0) =
                    make_float2(acc[mt][nt][0] + bb0, acc[mt][nt][1] + bb1);
            int edge1 = e0 + r0 + 8;
            if (edge1 < E)
                *(float2*)(out + (size_t)edge1 * OUT_DIM + c0) =
                    make_float2(acc[mt][nt][2] + bb0, acc[mt][nt][3] + bb1);
        }
}

extern "C" void kernel_launch(void* const* d_in, const int* in_sizes, int n_in,
                              void* d_out, int out_size) {
    const float* nf   = (const float*)d_in[0];
    const float* nh   = (const float*)d_in[1];
    const int*   srci = (const int*)d_in[2];
    const int*   dsti = (const int*)d_in[3];
    const float* dist = (const float*)d_in[4];
    const float* W1   = (const float*)d_in[5];
    const float* b1   = (const float*)d_in[6];
    const float* W2   = (const float*)d_in[7];
    const float* b2   = (const float*)d_in[8];
    const float* W3   = (const float*)d_in[9];
    const float* b3   = (const float*)d_in[10];
    float* out = (float*)d_out;
    int E = in_sizes[2];

    const int total_c = 160 * 512 + 32 * 512 + 512 * 512 / 2 + 512 * 256 / 2;
    conv_kernel<<<(total_c + 511) / 512, 512>>>(W1, W2, W3);

    const int pro_smem = (64 * 164 + 2 * 16 * 520) * (int)sizeof(float);
    cudaFuncSetAttribute(pdps_kernel, cudaFuncAttributeMaxDynamicSharedMemorySize, pro_smem);
    pdps_kernel<<<(NN + 63) / 64, 512, pro_smem>>>(nf, nh, b1);

    const int main_smem = SM_TOT * 4;
    cudaFuncSetAttribute(edge_kernel, cudaFuncAttributeMaxDynamicSharedMemorySize, main_smem);
    int grid = (E + E_TILE - 1) / E_TILE;
    edge_kernel<<<grid, THREADS, main_smem>>>(srci, dsti, dist, W1 + 320 * 512,
                                              b2, b3, out, E);
}